// round 12
// baseline (speedup 1.0000x reference)
#include <cuda_runtime.h>
#include <cstdint>
#include <math.h>

#define BS   8
#define NT   128
#define CH   1024
#define KH   4
#define HID  512
#define GD   2048
#define NGRP 8
#define MM   1024
#define NCTA_MAX 152

// ---- static device scratch ----
__device__ float4 g_Wa[8u*128*128*32];        // Wih frag-packed (67MB)
__device__ uint4  g_Wp[1024u*64*32];          // Whh unit-frag-packed (33.5MB)
__device__ float2 g_Xp[4u*128*128*32];        // inputs frag-packed (16.8MB)
__device__ float2 g_gates[(size_t)NGRP*GD*512]; // [grp][grow][m/2] (67MB)
__device__ float2 g_hbuf[129u*NGRP*2048];     // [t][grp][s*32+l] h history, tf32 (16.9MB)
__device__ float4 g_part[NCTA_MAX*7*32];      // k-split partial exchange
__device__ unsigned g_gbar[NGRP*32];          // per-group barriers (128B apart)

// ---- helpers ----
__device__ __forceinline__ uint32_t f2tf(float x) {
    uint32_t r; asm("cvt.rna.tf32.f32 %0, %1;" : "=r"(r) : "f"(x)); return r;
}
__device__ __forceinline__ void mma_tf32(float& c0, float& c1, float& c2, float& c3,
                                         uint32_t a0, uint32_t a1, uint32_t a2, uint32_t a3,
                                         uint32_t b0, uint32_t b1) {
    asm volatile("mma.sync.aligned.m16n8k8.row.col.f32.tf32.tf32.f32 "
        "{%0,%1,%2,%3}, {%4,%5,%6,%7}, {%8,%9}, {%0,%1,%2,%3};\n"
        : "+f"(c0), "+f"(c1), "+f"(c2), "+f"(c3)
        : "r"(a0), "r"(a1), "r"(a2), "r"(a3), "r"(b0), "r"(b1));
}
__device__ __forceinline__ float sigm(float x) { return 1.f / (1.f + __expf(-x)); }
__device__ __forceinline__ float tanh_f(float x) { return 2.f / (1.f + __expf(-2.f * x)) - 1.f; }

// ---------------------------------------------------------------------------
// Merged: barrier/h init + input B-frag pack (launch #0)
__global__ void setup_kernel(const float* __restrict__ in) {
    int idx = blockIdx.x * blockDim.x + threadIdx.x;
    if (idx < NGRP * 32) g_gbar[idx] = 0u;
    if (idx < NGRP * 2048) g_hbuf[idx] = make_float2(0.f, 0.f);   // h at t=0

    if (idx >= BS * NT * CH) return;
    int c  = idx % CH;
    int bt = idx / CH;
    int t  = bt % NT;
    int b  = bt / NT;
    float4 v = ((const float4*)in)[idx];
    int m = t * BS + b;
    int mblk = m >> 3, s = c >> 3;
    int l = ((m & 7) << 2) | (c & 3);
    int half = (c >> 2) & 1;
    float* xp = (float*)g_Xp;
    float vv[4] = {v.x, v.y, v.z, v.w};
#pragma unroll
    for (int kk = 0; kk < 4; kk++) {
        size_t fi = ((((size_t)kk * 128 + mblk) * 128 + s) * 32 + l) * 2 + half;
        xp[fi] = __uint_as_float(f2tf(vv[kk]));
    }
}

// ---------------------------------------------------------------------------
// Merged: Wih A-frag pack + Whh unit-frag pack (launch #1)
#define NWIH (8*128*128*32)
#define NWP  (1024*64*32)
__global__ void prepack_all(const float* __restrict__ Wih_f, const float* __restrict__ Wih_b,
                            const float* __restrict__ Whh_f, const float* __restrict__ Whh_b) {
    int t = blockIdx.x * blockDim.x + threadIdx.x;
    if (t < NWIH) {
        int l = t & 31, s = (t >> 5) & 127, g16 = (t >> 12) & 127, grp = t >> 19;
        int dir = grp >> 2, kh = grp & 3;
        const float* W = (dir ? Wih_b : Wih_f) + (size_t)kh * GD * CH;
        int r = g16 * 16 + (l >> 2);
        int c = s * 8 + (l & 3);
        float4 v;
        v.x = __uint_as_float(f2tf(W[(size_t)r * CH + c]));
        v.y = __uint_as_float(f2tf(W[(size_t)(r + 8) * CH + c]));
        v.z = __uint_as_float(f2tf(W[(size_t)r * CH + c + 4]));
        v.w = __uint_as_float(f2tf(W[(size_t)(r + 8) * CH + c + 4]));
        g_Wa[t] = v;
    } else {
        int q = t - NWIH;
        if (q >= NWP) return;
        int l = q & 31, s = (q >> 5) & 63, unit = q >> 11;
        int grp = unit >> 7, j4 = unit & 127;
        int dir = grp >> 2, kh = grp & 3;
        const float* W = (dir ? Whh_b : Whh_f) + (size_t)kh * GD * HID;
        int r = l >> 2;
        int grow0 = (r >> 2) * 512 + j4 * 4 + (r & 3);
        int grow1 = grow0 + 1024;
        int c = s * 8 + (l & 3);
        uint4 v;
        v.x = f2tf(W[(size_t)grow0 * HID + c]);
        v.y = f2tf(W[(size_t)grow1 * HID + c]);
        v.z = f2tf(W[(size_t)grow0 * HID + c + 4]);
        v.w = f2tf(W[(size_t)grow1 * HID + c + 4]);
        g_Wp[q] = v;
    }
}

// ---------------------------------------------------------------------------
// Input GEMM (tf32 mma), frags prepacked. CTA 128g x 128m, 8 warps. (launch #2)
__global__ void __launch_bounds__(256) input_gemm(
    const float* __restrict__ bih_f, const float* __restrict__ bhh_f,
    const float* __restrict__ bih_b, const float* __restrict__ bhh_b)
{
    int grp = blockIdx.z, dir = grp >> 2, kh = grp & 3;
    int tid = threadIdx.x, l = tid & 31, warp = tid >> 5;
    int wm = warp & 3, wn = warp >> 2;
    int t0  = blockIdx.y * 8 + wm * 2;
    int mb0 = blockIdx.x * 16 + wn * 8;

    const uint4*  A0 = (const uint4*)g_Wa + ((size_t)(grp * 128 + t0) * 128) * 32 + l;
    const uint4*  A1 = A0 + 128 * 32;
    const float2* Bp = g_Xp + ((size_t)(kh * 128 + mb0) * 128) * 32 + l;

    float c[2][8][4];
#pragma unroll
    for (int i = 0; i < 2; i++)
#pragma unroll
        for (int j = 0; j < 8; j++)
#pragma unroll
            for (int e = 0; e < 4; e++) c[i][j][e] = 0.f;

#pragma unroll 2
    for (int s = 0; s < 128; s++) {
        uint4 a0 = A0[(size_t)s * 32];
        uint4 a1 = A1[(size_t)s * 32];
        uint32_t bb0[8], bb1[8];
#pragma unroll
        for (int j = 0; j < 8; j++) {
            float2 bv = Bp[(size_t)j * 128 * 32 + (size_t)s * 32];
            bb0[j] = __float_as_uint(bv.x);
            bb1[j] = __float_as_uint(bv.y);
        }
#pragma unroll
        for (int j = 0; j < 8; j++) {
            mma_tf32(c[0][j][0], c[0][j][1], c[0][j][2], c[0][j][3],
                     a0.x, a0.y, a0.z, a0.w, bb0[j], bb1[j]);
            mma_tf32(c[1][j][0], c[1][j][1], c[1][j][2], c[1][j][3],
                     a1.x, a1.y, a1.z, a1.w, bb0[j], bb1[j]);
        }
    }

    const float* bi = (dir ? bih_b : bih_f) + kh * GD;
    const float* bh = (dir ? bhh_b : bhh_f) + kh * GD;
    int r0 = t0 * 16 + (l >> 2);
#pragma unroll
    for (int i = 0; i < 2; i++) {
        int ra = r0 + i * 16, rb = ra + 8;
        float ba = bi[ra] + bh[ra];
        float bbv = bi[rb] + bh[rb];
#pragma unroll
        for (int j = 0; j < 8; j++) {
            int mhalf = (mb0 + j) * 4 + (l & 3);
            g_gates[((size_t)grp * GD + ra) * 512 + mhalf] =
                make_float2(c[i][j][0] + ba, c[i][j][1] + ba);
            g_gates[((size_t)grp * GD + rb) * 512 + mhalf] =
                make_float2(c[i][j][2] + bbv, c[i][j][3] + bbv);
        }
    }
}

// ---------------------------------------------------------------------------
// Persistent recurrent kernel (launch #3). 512 threads; warp pair splits k.
// aligned=1 (152 SMs): 19 CTAs per group, per-group barrier (19 arrivals,
// no straddling). aligned=0: 148 CTAs, single global barrier (R7 fallback).
// Release/acquire barrier, no threadfence (bar.sync + red.release chain).
__global__ void __launch_bounds__(512) lstm_persistent(float* __restrict__ out, int aligned)
{
    extern __shared__ uint4 sW[];
    int tid = threadIdx.x, l = tid & 31, w = tid >> 5;
    int cta = blockIdx.x;

    int nu, ustart, bar;
    unsigned cnt;
    if (aligned) {
        int grp = cta / 19, loc = cta % 19;
        nu = (loc < 14) ? 7 : 6;
        ustart = grp * 128 + ((loc < 14) ? loc * 7 : 98 + (loc - 14) * 6);
        bar = grp; cnt = 19u;
    } else {
        nu = (cta < 136) ? 7 : 6;
        ustart = (cta < 136) ? cta * 7 : 952 + (cta - 136) * 6;
        bar = 0; cnt = 148u;
    }

    // load this CTA's weight units into smem
    {
        uint32_t sb = (uint32_t)__cvta_generic_to_shared(sW);
        const uint4* src = g_Wp + (size_t)ustart * 2048;
        int total = nu * 2048;
        for (int i = tid; i < total; i += 512) {
            asm volatile("cp.async.cg.shared.global [%0], [%1], 16;\n"
                         :: "r"(sb + i * 16), "l"(src + i));
        }
        asm volatile("cp.async.commit_group;\n");
        asm volatile("cp.async.wait_group 0;\n");
    }
    __syncthreads();

    int uu = w >> 1, khalf = w & 1;
    bool active = (uu < nu);
    int unit = ustart + (active ? uu : 0);
    int grp = unit >> 7, j4 = unit & 127;
    int dir = grp >> 2, kh = grp & 3;

    const uint4* wA = sW + uu * 2048 + khalf * 1024 + l;
    int r = l >> 2;
    int ga = (r >> 2) * 512 + j4 * 4 + (r & 3);
    const float2* ginA = g_gates + ((size_t)grp * GD + ga) * 512 + (l & 3);
    const float2* ginB = ginA + (size_t)1024 * 512;

    float4* pbuf = g_part + ((size_t)cta * 7 + uu) * 32;
    unsigned* barp = &g_gbar[bar * 32];

    int jj = r & 3;               // lanes<16: local j
    int b0 = (l & 3) * 2;
    int j  = j4 * 4 + jj;
    int s_ = j4 >> 1, half = j4 & 1;

    float cs0 = 0.f, cs1 = 0.f;

    for (int t = 0; t < NT; t++) {
        int tt = dir ? (NT - 1 - t) : t;
        float c0 = 0.f, c1 = 0.f, c2 = 0.f, c3 = 0.f;

        if (active) {
            const float2* hrd = g_hbuf + ((size_t)t * NGRP + grp) * 2048
                                + khalf * 1024 + l;
#pragma unroll 8
            for (int s = 0; s < 32; s++) {
                uint4 a = wA[s * 32];
                float2 hv = __ldg(hrd + s * 32);
                mma_tf32(c0, c1, c2, c3, a.x, a.y, a.z, a.w,
                         __float_as_uint(hv.x), __float_as_uint(hv.y));
            }
            if (khalf) pbuf[l] = make_float4(c0, c1, c2, c3);
        }
        __syncthreads();   // partials visible block-wide

        if (active && khalf == 0) {
            float4 p = pbuf[l];
            float2 ia = __ldg(ginA + tt * 4);
            float2 ib = __ldg(ginB + tt * 4);
            c0 += p.x + ia.x;
            c1 += p.y + ia.y;
            c2 += p.z + ib.x;
            c3 += p.w + ib.y;

            float r0 = __shfl_xor_sync(0xffffffffu, c0, 16);
            float r1 = __shfl_xor_sync(0xffffffffu, c1, 16);
            float r2 = __shfl_xor_sync(0xffffffffu, c2, 16);
            float r3 = __shfl_xor_sync(0xffffffffu, c3, 16);

            if (l < 16) {
                float i0 = sigm(c0), f0 = sigm(r0), g0 = tanh_f(c2), o0 = sigm(r2);
                cs0 = f0 * cs0 + i0 * g0;
                float hn0 = o0 * tanh_f(cs0);
                float i1 = sigm(c1), f1 = sigm(r1), g1 = tanh_f(c3), o1 = sigm(r3);
                cs1 = f1 * cs1 + i1 * g1;
                float hn1 = o1 * tanh_f(cs1);

                float* hw = (float*)(g_hbuf + ((size_t)(t + 1) * NGRP + grp) * 2048 + s_ * 32);
                hw[((b0 << 2) | jj) * 2 + half]       = __uint_as_float(f2tf(hn0));
                hw[(((b0 + 1) << 2) | jj) * 2 + half] = __uint_as_float(f2tf(hn1));

                out[(((size_t)b0 * NT + tt) * (2 * HID) + dir * HID + j) * KH + kh] = hn0;
                out[(((size_t)(b0 + 1) * NT + tt) * (2 * HID) + dir * HID + j) * KH + kh] = hn1;
            }
        }

        if (t < NT - 1) {
            __syncthreads();   // all CTA's h-stores happen-before thread 0's release
            if (tid == 0) {
                asm volatile("red.release.gpu.global.add.u32 [%0], %1;"
                             :: "l"(barp), "r"(1u) : "memory");
                unsigned target = cnt * (unsigned)(t + 1);
                unsigned v;
                do {
                    asm volatile("ld.global.acquire.gpu.b32 %0, [%1];"
                                 : "=r"(v) : "l"(barp));
                } while (v < target);
            }
            __syncthreads();   // acquire by thread 0 happens-before all reads
        }
    }
}

// ---------------------------------------------------------------------------
extern "C" void kernel_launch(void* const* d_in, const int* in_sizes, int n_in,
                              void* d_out, int out_size) {
    const float* inputs = (const float*)d_in[0];
    const float* Wih_f  = (const float*)d_in[1];
    const float* Whh_f  = (const float*)d_in[2];
    const float* bih_f  = (const float*)d_in[3];
    const float* bhh_f  = (const float*)d_in[4];
    const float* Wih_b  = (const float*)d_in[5];
    const float* Whh_b  = (const float*)d_in[6];
    const float* bih_b  = (const float*)d_in[7];
    const float* bhh_b  = (const float*)d_in[8];
    float* out = (float*)d_out;

    const int SMEM_BYTES = 7 * 2048 * 16;   // 229376
    cudaFuncSetAttribute(lstm_persistent, cudaFuncAttributeMaxDynamicSharedMemorySize, SMEM_BYTES);

    int sms = 0;
    cudaDeviceGetAttribute(&sms, cudaDevAttrMultiProcessorCount, 0);
    int aligned = (sms >= 152) ? 1 : 0;
    int grid = aligned ? 152 : 148;

    setup_kernel<<<(BS * NT * CH + 255) / 256, 256>>>(inputs);
    prepack_all<<<(NWIH + NWP + 255) / 256, 256>>>(Wih_f, Wih_b, Whh_f, Whh_b);
    input_gemm<<<dim3(8, 16, 8), 256>>>(bih_f, bhh_f, bih_b, bhh_b);
    lstm_persistent<<<grid, 512, SMEM_BYTES>>>(out, aligned);
}

// round 14
// speedup vs baseline: 1.0358x; 1.0358x over previous
#include <cuda_runtime.h>
#include <cstdint>
#include <math.h>

#define BS   8
#define NT   128
#define CH   1024
#define KH   4
#define HID  512
#define GD   2048
#define NGRP 8
#define MM   1024
#define NCTA 148

// ---- static device scratch ----
__device__ float4 g_Wa[8u*128*128*32];        // Wih frag-packed (67MB)
__device__ uint4  g_Wp[1024u*64*32];          // Whh unit-frag-packed (33.5MB)
__device__ float2 g_Xp[4u*128*128*32];        // inputs frag-packed (16.8MB)
__device__ float2 g_gates[(size_t)NGRP*GD*512]; // [grp][grow][m/2] (67MB)
__device__ float2 g_hbuf[129u*NGRP*2048];     // [t][grp][s*32+l] h history, tf32 (16.9MB)
__device__ float4 g_part[NCTA*7*32];          // k-split partial exchange
__device__ unsigned g_sub[8*32];              // 8 sub-counters, 128B apart
__device__ unsigned g_root;                   // root counter
__device__ unsigned g_epoch;                  // poll-only epoch line

// ---- helpers ----
__device__ __forceinline__ uint32_t f2tf(float x) {
    uint32_t r; asm("cvt.rna.tf32.f32 %0, %1;" : "=r"(r) : "f"(x)); return r;
}
__device__ __forceinline__ void mma_tf32(float& c0, float& c1, float& c2, float& c3,
                                         uint32_t a0, uint32_t a1, uint32_t a2, uint32_t a3,
                                         uint32_t b0, uint32_t b1) {
    asm volatile("mma.sync.aligned.m16n8k8.row.col.f32.tf32.tf32.f32 "
        "{%0,%1,%2,%3}, {%4,%5,%6,%7}, {%8,%9}, {%0,%1,%2,%3};\n"
        : "+f"(c0), "+f"(c1), "+f"(c2), "+f"(c3)
        : "r"(a0), "r"(a1), "r"(a2), "r"(a3), "r"(b0), "r"(b1));
}
__device__ __forceinline__ float sigm(float x) { return 1.f / (1.f + __expf(-x)); }
__device__ __forceinline__ float tanh_f(float x) { return 2.f / (1.f + __expf(-2.f * x)) - 1.f; }

// ---------------------------------------------------------------------------
// Merged: barrier/h init + input B-frag pack (launch #0)
__global__ void setup_kernel(const float* __restrict__ in) {
    int idx = blockIdx.x * blockDim.x + threadIdx.x;
    if (idx < 8 * 32) g_sub[idx] = 0u;
    if (idx == 0) { g_root = 0u; g_epoch = 0u; }
    if (idx < NGRP * 2048) g_hbuf[idx] = make_float2(0.f, 0.f);   // h at t=0

    if (idx >= BS * NT * CH) return;
    int c  = idx % CH;
    int bt = idx / CH;
    int t  = bt % NT;
    int b  = bt / NT;
    float4 v = ((const float4*)in)[idx];
    int m = t * BS + b;
    int mblk = m >> 3, s = c >> 3;
    int l = ((m & 7) << 2) | (c & 3);
    int half = (c >> 2) & 1;
    float* xp = (float*)g_Xp;
    float vv[4] = {v.x, v.y, v.z, v.w};
#pragma unroll
    for (int kk = 0; kk < 4; kk++) {
        size_t fi = ((((size_t)kk * 128 + mblk) * 128 + s) * 32 + l) * 2 + half;
        xp[fi] = __uint_as_float(f2tf(vv[kk]));
    }
}

// ---------------------------------------------------------------------------
// Merged: Wih A-frag pack + Whh unit-frag pack (launch #1)
#define NWIH (8*128*128*32)
#define NWP  (1024*64*32)
__global__ void prepack_all(const float* __restrict__ Wih_f, const float* __restrict__ Wih_b,
                            const float* __restrict__ Whh_f, const float* __restrict__ Whh_b) {
    int t = blockIdx.x * blockDim.x + threadIdx.x;
    if (t < NWIH) {
        int l = t & 31, s = (t >> 5) & 127, g16 = (t >> 12) & 127, grp = t >> 19;
        int dir = grp >> 2, kh = grp & 3;
        const float* W = (dir ? Wih_b : Wih_f) + (size_t)kh * GD * CH;
        int r = g16 * 16 + (l >> 2);
        int c = s * 8 + (l & 3);
        float4 v;
        v.x = __uint_as_float(f2tf(W[(size_t)r * CH + c]));
        v.y = __uint_as_float(f2tf(W[(size_t)(r + 8) * CH + c]));
        v.z = __uint_as_float(f2tf(W[(size_t)r * CH + c + 4]));
        v.w = __uint_as_float(f2tf(W[(size_t)(r + 8) * CH + c + 4]));
        g_Wa[t] = v;
    } else {
        int q = t - NWIH;
        if (q >= NWP) return;
        int l = q & 31, s = (q >> 5) & 63, unit = q >> 11;
        int grp = unit >> 7, j4 = unit & 127;
        int dir = grp >> 2, kh = grp & 3;
        const float* W = (dir ? Whh_b : Whh_f) + (size_t)kh * GD * HID;
        int r = l >> 2;
        int grow0 = (r >> 2) * 512 + j4 * 4 + (r & 3);
        int grow1 = grow0 + 1024;
        int c = s * 8 + (l & 3);
        uint4 v;
        v.x = f2tf(W[(size_t)grow0 * HID + c]);
        v.y = f2tf(W[(size_t)grow1 * HID + c]);
        v.z = f2tf(W[(size_t)grow0 * HID + c + 4]);
        v.w = f2tf(W[(size_t)grow1 * HID + c + 4]);
        g_Wp[q] = v;
    }
}

// ---------------------------------------------------------------------------
// Input GEMM (tf32 mma), frags prepacked. CTA 128g x 128m, 8 warps. (launch #2)
__global__ void __launch_bounds__(256) input_gemm(
    const float* __restrict__ bih_f, const float* __restrict__ bhh_f,
    const float* __restrict__ bih_b, const float* __restrict__ bhh_b)
{
    int grp = blockIdx.z, dir = grp >> 2, kh = grp & 3;
    int tid = threadIdx.x, l = tid & 31, warp = tid >> 5;
    int wm = warp & 3, wn = warp >> 2;
    int t0  = blockIdx.y * 8 + wm * 2;
    int mb0 = blockIdx.x * 16 + wn * 8;

    const uint4*  A0 = (const uint4*)g_Wa + ((size_t)(grp * 128 + t0) * 128) * 32 + l;
    const uint4*  A1 = A0 + 128 * 32;
    const float2* Bp = g_Xp + ((size_t)(kh * 128 + mb0) * 128) * 32 + l;

    float c[2][8][4];
#pragma unroll
    for (int i = 0; i < 2; i++)
#pragma unroll
        for (int j = 0; j < 8; j++)
#pragma unroll
            for (int e = 0; e < 4; e++) c[i][j][e] = 0.f;

#pragma unroll 2
    for (int s = 0; s < 128; s++) {
        uint4 a0 = A0[(size_t)s * 32];
        uint4 a1 = A1[(size_t)s * 32];
        uint32_t bb0[8], bb1[8];
#pragma unroll
        for (int j = 0; j < 8; j++) {
            float2 bv = Bp[(size_t)j * 128 * 32 + (size_t)s * 32];
            bb0[j] = __float_as_uint(bv.x);
            bb1[j] = __float_as_uint(bv.y);
        }
#pragma unroll
        for (int j = 0; j < 8; j++) {
            mma_tf32(c[0][j][0], c[0][j][1], c[0][j][2], c[0][j][3],
                     a0.x, a0.y, a0.z, a0.w, bb0[j], bb1[j]);
            mma_tf32(c[1][j][0], c[1][j][1], c[1][j][2], c[1][j][3],
                     a1.x, a1.y, a1.z, a1.w, bb0[j], bb1[j]);
        }
    }

    const float* bi = (dir ? bih_b : bih_f) + kh * GD;
    const float* bh = (dir ? bhh_b : bhh_f) + kh * GD;
    int r0 = t0 * 16 + (l >> 2);
#pragma unroll
    for (int i = 0; i < 2; i++) {
        int ra = r0 + i * 16, rb = ra + 8;
        float ba = bi[ra] + bh[ra];
        float bbv = bi[rb] + bh[rb];
#pragma unroll
        for (int j = 0; j < 8; j++) {
            int mhalf = (mb0 + j) * 4 + (l & 3);
            g_gates[((size_t)grp * GD + ra) * 512 + mhalf] =
                make_float2(c[i][j][0] + ba, c[i][j][1] + ba);
            g_gates[((size_t)grp * GD + rb) * 512 + mhalf] =
                make_float2(c[i][j][2] + bbv, c[i][j][3] + bbv);
        }
    }
}

// ---------------------------------------------------------------------------
// Persistent recurrent kernel (launch #3). 148 CTAs, 512 threads, k-split
// warp pairs (R11 structure). Barrier v3: hierarchical arrivals (8 padded
// sub-counters -> root), single poll-only epoch line. gin prefetched across
// the barrier.
__global__ void __launch_bounds__(512) lstm_persistent(float* __restrict__ out)
{
    extern __shared__ uint4 sW[];
    int tid = threadIdx.x, l = tid & 31, w = tid >> 5;
    int cta = blockIdx.x;
    int nu     = (cta < 136) ? 7 : 6;
    int ustart = (cta < 136) ? cta * 7 : 952 + (cta - 136) * 6;

    // load this CTA's weight units into smem
    {
        uint32_t sb = (uint32_t)__cvta_generic_to_shared(sW);
        const uint4* src = g_Wp + (size_t)ustart * 2048;
        int total = nu * 2048;
        for (int i = tid; i < total; i += 512) {
            asm volatile("cp.async.cg.shared.global [%0], [%1], 16;\n"
                         :: "r"(sb + i * 16), "l"(src + i));
        }
        asm volatile("cp.async.commit_group;\n");
        asm volatile("cp.async.wait_group 0;\n");
    }
    __syncthreads();

    int uu = w >> 1, khalf = w & 1;
    bool active = (uu < nu);
    int unit = ustart + (active ? uu : 0);
    int grp = unit >> 7, j4 = unit & 127;
    int dir = grp >> 2, kh = grp & 3;

    const uint4* wA = sW + uu * 2048 + khalf * 1024 + l;
    int r = l >> 2;
    int ga = (r >> 2) * 512 + j4 * 4 + (r & 3);
    const float2* ginA = g_gates + ((size_t)grp * GD + ga) * 512 + (l & 3);
    const float2* ginB = ginA + (size_t)1024 * 512;

    float4* pbuf = g_part + ((size_t)cta * 7 + uu) * 32;

    // barrier bookkeeping: 148 CTAs -> 8 sub-lines (subs 0-3: 19, 4-7: 18)
    int sub = cta & 7;
    unsigned subcnt = (sub < 4) ? 19u : 18u;

    int jj = r & 3;               // lanes<16: local j
    int b0 = (l & 3) * 2;
    int j  = j4 * 4 + jj;
    int s_ = j4 >> 1, half = j4 & 1;

    float cs0 = 0.f, cs1 = 0.f;

    // prefetch gin for step 0
    float2 ia = make_float2(0.f, 0.f), ib = make_float2(0.f, 0.f);
    if (active && khalf == 0) {
        int tt0 = dir ? (NT - 1) : 0;
        ia = __ldg(ginA + tt0 * 4);
        ib = __ldg(ginB + tt0 * 4);
    }

    for (int t = 0; t < NT; t++) {
        int tt = dir ? (NT - 1 - t) : t;
        float c0 = 0.f, c1 = 0.f, c2 = 0.f, c3 = 0.f;

        if (active) {
            const float2* hrd = g_hbuf + ((size_t)t * NGRP + grp) * 2048
                                + khalf * 1024 + l;
#pragma unroll 8
            for (int s = 0; s < 32; s++) {
                uint4 a = wA[s * 32];
                float2 hv = __ldg(hrd + s * 32);
                mma_tf32(c0, c1, c2, c3, a.x, a.y, a.z, a.w,
                         __float_as_uint(hv.x), __float_as_uint(hv.y));
            }
            if (khalf) pbuf[l] = make_float4(c0, c1, c2, c3);
        }
        __syncthreads();   // partials visible block-wide

        if (active && khalf == 0) {
            float4 p = pbuf[l];
            c0 += p.x + ia.x;
            c1 += p.y + ia.y;
            c2 += p.z + ib.x;
            c3 += p.w + ib.y;

            float r0 = __shfl_xor_sync(0xffffffffu, c0, 16);
            float r1 = __shfl_xor_sync(0xffffffffu, c1, 16);
            float r2 = __shfl_xor_sync(0xffffffffu, c2, 16);
            float r3 = __shfl_xor_sync(0xffffffffu, c3, 16);

            if (l < 16) {
                float i0 = sigm(c0), f0 = sigm(r0), g0 = tanh_f(c2), o0 = sigm(r2);
                cs0 = f0 * cs0 + i0 * g0;
                float hn0 = o0 * tanh_f(cs0);
                float i1 = sigm(c1), f1 = sigm(r1), g1 = tanh_f(c3), o1 = sigm(r3);
                cs1 = f1 * cs1 + i1 * g1;
                float hn1 = o1 * tanh_f(cs1);

                float* hw = (float*)(g_hbuf + ((size_t)(t + 1) * NGRP + grp) * 2048 + s_ * 32);
                hw[((b0 << 2) | jj) * 2 + half]       = __uint_as_float(f2tf(hn0));
                hw[(((b0 + 1) << 2) | jj) * 2 + half] = __uint_as_float(f2tf(hn1));

                out[(((size_t)b0 * NT + tt) * (2 * HID) + dir * HID + j) * KH + kh] = hn0;
                out[(((size_t)(b0 + 1) * NT + tt) * (2 * HID) + dir * HID + j) * KH + kh] = hn1;
            }
        }

        if (t < NT - 1) {
            // prefetch next-step gin (read-only data; in flight during barrier)
            if (active && khalf == 0) {
                int ttn = dir ? (NT - 2 - t) : (t + 1);
                ia = __ldg(ginA + ttn * 4);
                ib = __ldg(ginB + ttn * 4);
            }
            __threadfence();
            __syncthreads();
            unsigned tstep = (unsigned)(t + 1);
            if (tid == 0) {
                // hierarchical arrival: sub -> root -> epoch (release)
                unsigned old = atomicAdd(&g_sub[sub * 32], 1u);
                if (old == subcnt * tstep - 1u) {
                    unsigned old2 = atomicAdd(&g_root, 1u);
                    if (old2 == 8u * tstep - 1u) {
                        asm volatile("st.global.release.gpu.b32 [%0], %1;"
                                     :: "l"(&g_epoch), "r"(tstep) : "memory");
                    }
                }
                // poll the read-only epoch line
                unsigned v;
                do {
                    asm volatile("ld.global.acquire.gpu.b32 %0, [%1];"
                                 : "=r"(v) : "l"(&g_epoch));
                } while (v < tstep);
            }
            __syncthreads();
        }
    }
}

// ---------------------------------------------------------------------------
extern "C" void kernel_launch(void* const* d_in, const int* in_sizes, int n_in,
                              void* d_out, int out_size) {
    const float* inputs = (const float*)d_in[0];
    const float* Wih_f  = (const float*)d_in[1];
    const float* Whh_f  = (const float*)d_in[2];
    const float* bih_f  = (const float*)d_in[3];
    const float* bhh_f  = (const float*)d_in[4];
    const float* Wih_b  = (const float*)d_in[5];
    const float* Whh_b  = (const float*)d_in[6];
    const float* bih_b  = (const float*)d_in[7];
    const float* bhh_b  = (const float*)d_in[8];
    float* out = (float*)d_out;

    const int SMEM_BYTES = 7 * 2048 * 16;   // 229376
    cudaFuncSetAttribute(lstm_persistent, cudaFuncAttributeMaxDynamicSharedMemorySize, SMEM_BYTES);

    setup_kernel<<<(BS * NT * CH + 255) / 256, 256>>>(inputs);
    prepack_all<<<(NWIH + NWP + 255) / 256, 256>>>(Wih_f, Wih_b, Whh_f, Whh_b);
    input_gemm<<<dim3(8, 16, 8), 256>>>(bih_f, bhh_f, bih_b, bhh_b);
    lstm_persistent<<<NCTA, 512, SMEM_BYTES>>>(out);
}

// round 15
// speedup vs baseline: 1.3819x; 1.3341x over previous
#include <cuda_runtime.h>
#include <cstdint>
#include <math.h>

#define BS   8
#define NT   128
#define CH   1024
#define KH   4
#define HID  512
#define GD   2048
#define NGRP 8
#define MM   1024
#define NCTA 148

// ---- static device scratch ----
__device__ float4 g_Wa[8u*128*128*32];        // Wih frag-packed (67MB)
__device__ uint4  g_Wp[1024u*64*32];          // Whh unit-frag-packed (33.5MB)
__device__ float2 g_Xp[4u*128*128*32];        // inputs frag-packed (16.8MB)
__device__ float2 g_gates[(size_t)NGRP*GD*512]; // [grp][grow][m/2] (67MB)
__device__ float2 g_hbuf[129u*NGRP*2048];     // [t][grp][s*32+l] h history, tf32 (16.9MB)
__device__ float4 g_part[NCTA*7*32];          // k-split partial exchange
__device__ unsigned g_bar;                    // single global barrier (R11-proven)

// ---- helpers ----
__device__ __forceinline__ uint32_t f2tf(float x) {
    uint32_t r; asm("cvt.rna.tf32.f32 %0, %1;" : "=r"(r) : "f"(x)); return r;
}
__device__ __forceinline__ void mma_tf32(float& c0, float& c1, float& c2, float& c3,
                                         uint32_t a0, uint32_t a1, uint32_t a2, uint32_t a3,
                                         uint32_t b0, uint32_t b1) {
    asm volatile("mma.sync.aligned.m16n8k8.row.col.f32.tf32.tf32.f32 "
        "{%0,%1,%2,%3}, {%4,%5,%6,%7}, {%8,%9}, {%0,%1,%2,%3};\n"
        : "+f"(c0), "+f"(c1), "+f"(c2), "+f"(c3)
        : "r"(a0), "r"(a1), "r"(a2), "r"(a3), "r"(b0), "r"(b1));
}
__device__ __forceinline__ float sigm(float x) { return 1.f / (1.f + __expf(-x)); }
__device__ __forceinline__ float tanh_f(float x) { return 2.f / (1.f + __expf(-2.f * x)) - 1.f; }

// ---------------------------------------------------------------------------
// Merged: barrier/h init + input B-frag pack (launch #0)
__global__ void setup_kernel(const float* __restrict__ in) {
    int idx = blockIdx.x * blockDim.x + threadIdx.x;
    if (idx == 0) g_bar = 0u;
    if (idx < NGRP * 2048) g_hbuf[idx] = make_float2(0.f, 0.f);   // h at t=0

    if (idx >= BS * NT * CH) return;
    int c  = idx % CH;
    int bt = idx / CH;
    int t  = bt % NT;
    int b  = bt / NT;
    float4 v = ((const float4*)in)[idx];
    int m = t * BS + b;
    int mblk = m >> 3, s = c >> 3;
    int l = ((m & 7) << 2) | (c & 3);
    int half = (c >> 2) & 1;
    float* xp = (float*)g_Xp;
    float vv[4] = {v.x, v.y, v.z, v.w};
#pragma unroll
    for (int kk = 0; kk < 4; kk++) {
        size_t fi = ((((size_t)kk * 128 + mblk) * 128 + s) * 32 + l) * 2 + half;
        xp[fi] = __uint_as_float(f2tf(vv[kk]));
    }
}

// ---------------------------------------------------------------------------
// Merged: Wih A-frag pack + Whh unit-frag pack (launch #1)
#define NWIH (8*128*128*32)
#define NWP  (1024*64*32)
__global__ void prepack_all(const float* __restrict__ Wih_f, const float* __restrict__ Wih_b,
                            const float* __restrict__ Whh_f, const float* __restrict__ Whh_b) {
    int t = blockIdx.x * blockDim.x + threadIdx.x;
    if (t < NWIH) {
        int l = t & 31, s = (t >> 5) & 127, g16 = (t >> 12) & 127, grp = t >> 19;
        int dir = grp >> 2, kh = grp & 3;
        const float* W = (dir ? Wih_b : Wih_f) + (size_t)kh * GD * CH;
        int r = g16 * 16 + (l >> 2);
        int c = s * 8 + (l & 3);
        float4 v;
        v.x = __uint_as_float(f2tf(W[(size_t)r * CH + c]));
        v.y = __uint_as_float(f2tf(W[(size_t)(r + 8) * CH + c]));
        v.z = __uint_as_float(f2tf(W[(size_t)r * CH + c + 4]));
        v.w = __uint_as_float(f2tf(W[(size_t)(r + 8) * CH + c + 4]));
        g_Wa[t] = v;
    } else {
        int q = t - NWIH;
        if (q >= NWP) return;
        int l = q & 31, s = (q >> 5) & 63, unit = q >> 11;
        int grp = unit >> 7, j4 = unit & 127;
        int dir = grp >> 2, kh = grp & 3;
        const float* W = (dir ? Whh_b : Whh_f) + (size_t)kh * GD * HID;
        int r = l >> 2;
        int grow0 = (r >> 2) * 512 + j4 * 4 + (r & 3);
        int grow1 = grow0 + 1024;
        int c = s * 8 + (l & 3);
        uint4 v;
        v.x = f2tf(W[(size_t)grow0 * HID + c]);
        v.y = f2tf(W[(size_t)grow1 * HID + c]);
        v.z = f2tf(W[(size_t)grow0 * HID + c + 4]);
        v.w = f2tf(W[(size_t)grow1 * HID + c + 4]);
        g_Wp[q] = v;
    }
}

// ---------------------------------------------------------------------------
// Input GEMM v2 (launch #2): 3-stage cp.async smem pipeline.
// CTA tile 128g x 256m, BK=32. Grid (4, 16, 8). 8 warps = 2(g) x 4(m),
// warp tile 64g x 64m = 4 m16 x 8 n8. Stages hold fragment-packed chunks:
//   sA: 8 g16-tiles x 4 s x 32 l (uint4)  = 16KB
//   sB: 32 mblk    x 4 s x 32 l (float2)  = 32KB
// Stage = 3072 x 16B chunks; 3 stages = 144KB smem.
#define GS_CHUNKS 3072
#define NIT 32

__device__ __forceinline__ void gemm_load_stage(
    int it, int stg, int grp, int kh, int by, int bx, int tid, uint4* sG)
{
    uint32_t sb = (uint32_t)__cvta_generic_to_shared(sG + stg * GS_CHUNKS);
    const uint4* Wa4 = (const uint4*)g_Wa;
#pragma unroll
    for (int e = 0; e < GS_CHUNKS / 256; e++) {
        int i = e * 256 + tid;
        const void* src;
        if (i < 1024) {
            int tile = i >> 7, off = i & 127;
            src = Wa4 + (((size_t)(grp * 128 + by * 8 + tile) * 128 + it * 4) * 32) + off;
        } else {
            int jj = i - 1024;
            int mblk = jj >> 6, off = jj & 63;
            src = (const float2*)g_Xp
                  + (((size_t)(kh * 128 + bx * 32 + mblk) * 128 + it * 4) * 32) + off * 2;
        }
        asm volatile("cp.async.cg.shared.global [%0], [%1], 16;\n"
                     :: "r"(sb + i * 16), "l"(src));
    }
    asm volatile("cp.async.commit_group;\n");
}

__global__ void __launch_bounds__(256) input_gemm(
    const float* __restrict__ bih_f, const float* __restrict__ bhh_f,
    const float* __restrict__ bih_b, const float* __restrict__ bhh_b)
{
    extern __shared__ uint4 sG[];
    int grp = blockIdx.z, dir = grp >> 2, kh = grp & 3;
    int by = blockIdx.y, bx = blockIdx.x;
    int tid = threadIdx.x, l = tid & 31, warp = tid >> 5;
    int wm = warp & 1, wn = warp >> 1;

    gemm_load_stage(0, 0, grp, kh, by, bx, tid, sG);
    gemm_load_stage(1, 1, grp, kh, by, bx, tid, sG);

    float acc[4][8][4];
#pragma unroll
    for (int i = 0; i < 4; i++)
#pragma unroll
        for (int j = 0; j < 8; j++)
#pragma unroll
            for (int e = 0; e < 4; e++) acc[i][j][e] = 0.f;

    for (int it = 0; it < NIT; it++) {
        if (it < NIT - 1) asm volatile("cp.async.wait_group 1;\n");
        else             asm volatile("cp.async.wait_group 0;\n");
        __syncthreads();
        if (it + 2 < NIT) gemm_load_stage(it + 2, (it + 2) % 3, grp, kh, by, bx, tid, sG);

        int stg = it % 3;
        const uint4*  sA = sG + stg * GS_CHUNKS;
        const float2* sB = (const float2*)(sG + stg * GS_CHUNKS + 1024);
#pragma unroll
        for (int s = 0; s < 4; s++) {
            uint4 aa[4];
            uint32_t b0[8], b1[8];
#pragma unroll
            for (int i = 0; i < 4; i++)
                aa[i] = sA[(wm * 4 + i) * 128 + s * 32 + l];
#pragma unroll
            for (int j = 0; j < 8; j++) {
                float2 bv = sB[(wn * 8 + j) * 128 + s * 32 + l];
                b0[j] = __float_as_uint(bv.x);
                b1[j] = __float_as_uint(bv.y);
            }
#pragma unroll
            for (int i = 0; i < 4; i++)
#pragma unroll
                for (int j = 0; j < 8; j++)
                    mma_tf32(acc[i][j][0], acc[i][j][1], acc[i][j][2], acc[i][j][3],
                             aa[i].x, aa[i].y, aa[i].z, aa[i].w, b0[j], b1[j]);
        }
        __syncthreads();
    }

    const float* bi = (dir ? bih_b : bih_f) + kh * GD;
    const float* bh = (dir ? bhh_b : bhh_f) + kh * GD;
#pragma unroll
    for (int i = 0; i < 4; i++) {
        int g16 = by * 8 + wm * 4 + i;
        int ra = g16 * 16 + (l >> 2), rb = ra + 8;
        float ba  = bi[ra] + bh[ra];
        float bbv = bi[rb] + bh[rb];
#pragma unroll
        for (int j = 0; j < 8; j++) {
            int mhalf = (bx * 32 + wn * 8 + j) * 4 + (l & 3);
            g_gates[((size_t)grp * GD + ra) * 512 + mhalf] =
                make_float2(acc[i][j][0] + ba, acc[i][j][1] + ba);
            g_gates[((size_t)grp * GD + rb) * 512 + mhalf] =
                make_float2(acc[i][j][2] + bbv, acc[i][j][3] + bbv);
        }
    }
}

// ---------------------------------------------------------------------------
// Persistent recurrent kernel (launch #3) — EXACT R11 structure (best: ~650us).
// 148 CTAs, 512 threads, k-split warp pairs, single global barrier with
// threadfence + atomicAdd + acquire poll.
__global__ void __launch_bounds__(512) lstm_persistent(float* __restrict__ out)
{
    extern __shared__ uint4 sW[];
    int tid = threadIdx.x, l = tid & 31, w = tid >> 5;
    int cta = blockIdx.x;
    int nu     = (cta < 136) ? 7 : 6;
    int ustart = (cta < 136) ? cta * 7 : 952 + (cta - 136) * 6;

    // load this CTA's weight units into smem
    {
        uint32_t sb = (uint32_t)__cvta_generic_to_shared(sW);
        const uint4* src = g_Wp + (size_t)ustart * 2048;
        int total = nu * 2048;
        for (int i = tid; i < total; i += 512) {
            asm volatile("cp.async.cg.shared.global [%0], [%1], 16;\n"
                         :: "r"(sb + i * 16), "l"(src + i));
        }
        asm volatile("cp.async.commit_group;\n");
        asm volatile("cp.async.wait_group 0;\n");
    }
    __syncthreads();

    int uu = w >> 1, khalf = w & 1;
    bool active = (uu < nu);
    int unit = ustart + (active ? uu : 0);
    int grp = unit >> 7, j4 = unit & 127;
    int dir = grp >> 2, kh = grp & 3;

    const uint4* wA = sW + uu * 2048 + khalf * 1024 + l;
    int r = l >> 2;
    int ga = (r >> 2) * 512 + j4 * 4 + (r & 3);
    const float2* ginA = g_gates + ((size_t)grp * GD + ga) * 512 + (l & 3);
    const float2* ginB = ginA + (size_t)1024 * 512;

    float4* pbuf = g_part + ((size_t)cta * 7 + uu) * 32;

    int jj = r & 3;               // lanes<16: local j
    int b0 = (l & 3) * 2;
    int j  = j4 * 4 + jj;
    int s_ = j4 >> 1, half = j4 & 1;

    float cs0 = 0.f, cs1 = 0.f;

    for (int t = 0; t < NT; t++) {
        int tt = dir ? (NT - 1 - t) : t;
        float c0 = 0.f, c1 = 0.f, c2 = 0.f, c3 = 0.f;

        if (active) {
            const float2* hrd = g_hbuf + ((size_t)t * NGRP + grp) * 2048
                                + khalf * 1024 + l;
#pragma unroll 8
            for (int s = 0; s < 32; s++) {
                uint4 a = wA[s * 32];
                float2 hv = __ldg(hrd + s * 32);
                mma_tf32(c0, c1, c2, c3, a.x, a.y, a.z, a.w,
                         __float_as_uint(hv.x), __float_as_uint(hv.y));
            }
            if (khalf) pbuf[l] = make_float4(c0, c1, c2, c3);
        }
        __syncthreads();   // partials visible block-wide

        if (active && khalf == 0) {
            float4 p = pbuf[l];
            float2 ia = __ldg(ginA + tt * 4);
            float2 ib = __ldg(ginB + tt * 4);
            c0 += p.x + ia.x;
            c1 += p.y + ia.y;
            c2 += p.z + ib.x;
            c3 += p.w + ib.y;

            float r0 = __shfl_xor_sync(0xffffffffu, c0, 16);
            float r1 = __shfl_xor_sync(0xffffffffu, c1, 16);
            float r2 = __shfl_xor_sync(0xffffffffu, c2, 16);
            float r3 = __shfl_xor_sync(0xffffffffu, c3, 16);

            if (l < 16) {
                float i0 = sigm(c0), f0 = sigm(r0), g0 = tanh_f(c2), o0 = sigm(r2);
                cs0 = f0 * cs0 + i0 * g0;
                float hn0 = o0 * tanh_f(cs0);
                float i1 = sigm(c1), f1 = sigm(r1), g1 = tanh_f(c3), o1 = sigm(r3);
                cs1 = f1 * cs1 + i1 * g1;
                float hn1 = o1 * tanh_f(cs1);

                float* hw = (float*)(g_hbuf + ((size_t)(t + 1) * NGRP + grp) * 2048 + s_ * 32);
                hw[((b0 << 2) | jj) * 2 + half]       = __uint_as_float(f2tf(hn0));
                hw[(((b0 + 1) << 2) | jj) * 2 + half] = __uint_as_float(f2tf(hn1));

                out[(((size_t)b0 * NT + tt) * (2 * HID) + dir * HID + j) * KH + kh] = hn0;
                out[(((size_t)(b0 + 1) * NT + tt) * (2 * HID) + dir * HID + j) * KH + kh] = hn1;
            }
        }

        if (t < NT - 1) {
            __threadfence();
            __syncthreads();
            if (tid == 0) {
                atomicAdd(&g_bar, 1u);
                unsigned target = (unsigned)NCTA * (t + 1);
                unsigned v;
                do {
                    asm volatile("ld.global.acquire.gpu.b32 %0, [%1];"
                                 : "=r"(v) : "l"(&g_bar));
                } while (v < target);
            }
            __syncthreads();
        }
    }
}

// ---------------------------------------------------------------------------
extern "C" void kernel_launch(void* const* d_in, const int* in_sizes, int n_in,
                              void* d_out, int out_size) {
    const float* inputs = (const float*)d_in[0];
    const float* Wih_f  = (const float*)d_in[1];
    const float* Whh_f  = (const float*)d_in[2];
    const float* bih_f  = (const float*)d_in[3];
    const float* bhh_f  = (const float*)d_in[4];
    const float* Wih_b  = (const float*)d_in[5];
    const float* Whh_b  = (const float*)d_in[6];
    const float* bih_b  = (const float*)d_in[7];
    const float* bhh_b  = (const float*)d_in[8];
    float* out = (float*)d_out;

    const int SMEM_PERS = 7 * 2048 * 16;        // 229376
    const int SMEM_GEMM = 3 * GS_CHUNKS * 16;   // 147456
    cudaFuncSetAttribute(lstm_persistent, cudaFuncAttributeMaxDynamicSharedMemorySize, SMEM_PERS);
    cudaFuncSetAttribute(input_gemm, cudaFuncAttributeMaxDynamicSharedMemorySize, SMEM_GEMM);

    setup_kernel<<<(BS * NT * CH + 255) / 256, 256>>>(inputs);
    prepack_all<<<(NWIH + NWP + 255) / 256, 256>>>(Wih_f, Wih_b, Whh_f, Whh_b);
    input_gemm<<<dim3(4, 16, 8), 256, SMEM_GEMM>>>(bih_f, bhh_f, bih_b, bhh_b);
    lstm_persistent<<<NCTA, 512, SMEM_PERS>>>(out);
}